// round 11
// baseline (speedup 1.0000x reference)
#include <cuda_runtime.h>
#include <cstdint>

// Problem constants
#define BB 32
#define SS 2048
#define HH 32
#define NOPE 128
#define VD 128
#define HID 4096
#define QKVN 12288              // 4096 q (compact nope) + 4096 k + 4096 v
#define SCALE 0.08838834764831843f   // 128^-0.5

#define NCHUNK 8
#define CHUNK 256

#define SPLIT1 16               // GEMM1 split-K
#define SPLIT2 16               // GEMM2 split-K

// ---------------- scratch (static device globals; no runtime alloc) -------------
__device__ float g_p1[(size_t)SPLIT1 * 32u * 12288u];   // GEMM1 partials (25 MB)
__device__ float g_qkv[32u * 12288u];            // fused q/k/v projections
__device__ float g_pm[1024 * NCHUNK];            // per-(b,h,chunk) running max
__device__ float g_pl[1024 * NCHUNK];            // per-(b,h,chunk) exp-sum
__device__ float g_pacc[1024 * NCHUNK * 128];    // per-chunk weighted V (4 MB)
__device__ float g_attn[32u * 4096u];            // attention output [B][H*VD]
__device__ float g_p2[(size_t)SPLIT2 * 32u * 4096u];    // GEMM2 partials (8.4 MB)

// packed f32x2 fma (Blackwell sm_100+); doubles fp32 FMA throughput
__device__ __forceinline__ unsigned long long ffma2(unsigned long long a,
                                                    unsigned long long b,
                                                    unsigned long long c) {
    unsigned long long d;
    asm("fma.rn.f32x2 %0, %1, %2, %3;" : "=l"(d) : "l"(a), "l"(b), "l"(c));
    return d;
}

// ---------------- prep kernels (also place gemm1 in ncu's profiled slot 4) ------
__global__ void zero_pl_kernel() { g_pl[blockIdx.x * 256 + threadIdx.x] = 0.f; }
__global__ void zero_pm0_kernel() { g_pm[blockIdx.x * 256 + threadIdx.x] = -1e30f; }
__global__ void zero_pm1_kernel() {
    g_pm[4096 + blockIdx.x * 256 + threadIdx.x] = -1e30f;
}

// =====================================================================
// GEMM v5 (occupancy-first): C[32][N] = A[32][4096] @ W[N][4096]^T.
// v4 was register-capped at 16 warps/SM (128 regs) -> issue 41%, fma 44%.
// v5 tiles 8M x 4N per thread: acc = 16 u64 (32 regs), ~70 regs total,
// __launch_bounds__(256,3) -> 24 warps/SM. Operands need ZERO packing ops:
//   - W in smem TRANSPOSED [kk][n], rows 260 floats (skew 4): compute reads
//     LDS.64 (n,n+1)-pairs straight into f32x2 B-operands; staging STS ~2-way.
//   - A in smem PRE-DUPLICATED [kk][2m]: 4 broadcast LDS.128 give dup'd
//     a-operands directly.
// Inner loop per kk: 16 FFMA2 + 6 LDS (73% fma mix, 6 wf per 16 FFMA2).
// W/A global loads register-double-buffered across k-steps (BK=16),
// smem double-buffered, one barrier per step. Epilogue: coalesced STG.64.
// MODE 0: W = fused Wq(nope-compact rows)+Wkv virtual rows, -> g_p1.
// MODE 1: W = Wo, A = g_attn, -> g_p2.
// Block: 256 thr; warp w: m-oct (w>>1)*8, n-half (w&1)*128.
// =====================================================================
#define WROW 260                 // skewed W smem row (floats)
template <int MODE>
__global__ void __launch_bounds__(256, 3) gemm_kernel(
    const float* __restrict__ A, const float* __restrict__ W0,
    const float* __restrict__ W1, int N, int ksteps, float* __restrict__ part) {
    extern __shared__ __align__(16) float smem[];
    float* Wsm = smem;                       // [2][16][WROW]
    float* Asm = smem + 2 * 16 * WROW;       // [2][16][64] duplicated

    const int t = threadIdx.x;
    const int w = t >> 5, l = t & 31;
    const int n0 = blockIdx.x * 256;
    const int kbase = blockIdx.y * (ksteps * 16);
    const float* Ap = (MODE == 0) ? A : g_attn;

    const int g = w >> 1;            // m-oct (8 rows: 8g..8g+7)
    const int nb = (w & 1) * 128;    // n-half base

    // W staging: 4 lanes per row (quad wq), rows wr = t>>2 (64/pass, 4 passes)
    const int wr = t >> 2;
    const int wq = t & 3;
    const float* wptr[4];
#pragma unroll
    for (int p = 0; p < 4; p++) {
        int n = n0 + p * 64 + wr;
        const float* row;
        if (MODE == 0)
            row = (n < 4096) ? W0 + (size_t)((n >> 7) * 192 + (n & 127)) * HID
                             : W1 + (size_t)(n - 4096) * HID;
        else
            row = W0 + (size_t)n * HID;
        wptr[p] = row + kbase + 4 * wq;
    }
    // A staging: thread (m = t&31, k-pair = (t>>5)*2)
    const int am = t & 31;
    const int ak2 = (t >> 5) * 2;
    const float* aptr = Ap + (size_t)am * HID + kbase + ak2;

    unsigned long long acc[16];   // [jp*8 + m8] = (C[m][n], C[m][n+1])
#pragma unroll
    for (int i = 0; i < 16; i++) acc[i] = 0ull;

    // prologue prefetch (step 0)
    float4 wv[4];
    float2 av;
#pragma unroll
    for (int p = 0; p < 4; p++) wv[p] = *(const float4*)wptr[p];
    av = *(const float2*)aptr;

    for (int ks = 0; ks < ksteps; ks++) {
        const int buf = ks & 1;
        float* Wb = Wsm + buf * 16 * WROW;
        float* Ab = Asm + buf * 16 * 64;

        // ---- stage regs -> smem (W transposed, A duplicated) ----
#pragma unroll
        for (int p = 0; p < 4; p++)
#pragma unroll
            for (int i = 0; i < 4; i++)
                Wb[(4 * wq + i) * WROW + p * 64 + wr] = (&wv[p].x)[i];
        *(float2*)(Ab + ak2 * 64 + 2 * am) = make_float2(av.x, av.x);
        *(float2*)(Ab + (ak2 + 1) * 64 + 2 * am) = make_float2(av.y, av.y);
        __syncthreads();

        // ---- prefetch next step into regs (hidden under compute) ----
        if (ks + 1 < ksteps) {
#pragma unroll
            for (int p = 0; p < 4; p++)
                wv[p] = *(const float4*)(wptr[p] + (ks + 1) * 16);
            av = *(const float2*)(aptr + (ks + 1) * 16);
        }

        // ---- compute 16 kk ----
#pragma unroll
        for (int kk = 0; kk < 16; kk++) {
            const float* ar = Ab + kk * 64 + 16 * g;
            unsigned long long ad[8];
#pragma unroll
            for (int j = 0; j < 4; j++) {
                ulonglong2 v = *(const ulonglong2*)(ar + 4 * j);
                ad[2 * j] = v.x;
                ad[2 * j + 1] = v.y;
            }
            const float* wrp = Wb + kk * WROW + nb + 2 * l;
            unsigned long long w0 = *(const unsigned long long*)wrp;
            unsigned long long w1 = *(const unsigned long long*)(wrp + 64);
#pragma unroll
            for (int m8 = 0; m8 < 8; m8++) {
                acc[m8] = ffma2(ad[m8], w0, acc[m8]);
                acc[8 + m8] = ffma2(ad[m8], w1, acc[8 + m8]);
            }
        }
        __syncthreads();   // readers done before next step's STS reuses buf
    }

    // ---- epilogue: coalesced STG.64 (n-pairs) ----
#pragma unroll
    for (int jp = 0; jp < 2; jp++) {
        int col = n0 + nb + 2 * l + 64 * jp;
#pragma unroll
        for (int m8 = 0; m8 < 8; m8++) {
            int m = 8 * g + m8;
            *(unsigned long long*)(part +
                                   ((size_t)blockIdx.y * 32 + m) * N + col) =
                acc[jp * 8 + m8];
        }
    }
}

// sum the SPLIT1 GEMM1 split-K partials -> g_qkv
__global__ void reduce_qkv_kernel() {
    int i = blockIdx.x * 256 + threadIdx.x;   // 393216 total
    float s = 0.f;
#pragma unroll
    for (int c = 0; c < SPLIT1; c++) s += g_p1[(size_t)c * 393216 + i];
    g_qkv[i] = s;
}

// =====================================================================
// Flash-decoding attention partial (AT THE MEMORY WALL: 80% DRAM, ~96%
// of the 6.35 TB/s LTS cap — unchanged). One block per (b,h,chunk).
// =====================================================================
__global__ void __launch_bounds__(256) attn_partial_kernel(
    const float* __restrict__ k_cache, const float* __restrict__ v_cache,
    const int* __restrict__ positions) {
    const int bh = blockIdx.x;
    const int c = blockIdx.y;
    const int b = bh >> 5, h = bh & 31;
    const int t = threadIdx.x, lane = t & 31, w = t >> 5;
    const int pos = positions[b];
    const int L = pos + 1;
    const int s0 = c * CHUNK;
    const int len = min(CHUNK, L - s0);
    const int pidx = bh * NCHUNK + c;
    if (len <= 0) return;   // g_pl pre-zeroed by prep kernel

    __shared__ float sc[CHUNK];
    __shared__ float red[256];
    __shared__ float redw[8];
    __shared__ float s_m, s_l;

    const float* qb = g_qkv + b * QKVN + h * 128;
    const float4 q4 = *(const float4*)(qb + lane * 4);
    const float* knew = g_qkv + b * QKVN + 4096 + h * 128;
    const float* kbasep = k_cache + (size_t)b * SS * (HH * 128) + h * 128;

    for (int sl = 4 * w; sl < len; sl += 32) {
        float4 kv[4];
        float dd[4];
#pragma unroll
        for (int i = 0; i < 4; i++) {
            int sli = sl + i;
            int s = s0 + sli;
            const float* kp = (sli < len)
                                  ? ((s == pos) ? knew
                                                : (kbasep + (size_t)s * 4096))
                                  : knew;   // safe dummy
            kv[i] = *(const float4*)(kp + lane * 4);
        }
#pragma unroll
        for (int i = 0; i < 4; i++)
            dd[i] = kv[i].x * q4.x + kv[i].y * q4.y + kv[i].z * q4.z +
                    kv[i].w * q4.w;
#pragma unroll
        for (int o = 16; o; o >>= 1) {
#pragma unroll
            for (int i = 0; i < 4; i++)
                dd[i] += __shfl_xor_sync(0xffffffffu, dd[i], o);
        }
        if (lane == 0) {
#pragma unroll
            for (int i = 0; i < 4; i++)
                if (sl + i < len) sc[sl + i] = dd[i] * SCALE;
        }
    }
    __syncthreads();

    float lm = (t < len) ? sc[t] : -1e30f;
#pragma unroll
    for (int o = 16; o; o >>= 1) lm = fmaxf(lm, __shfl_xor_sync(0xffffffffu, lm, o));
    if (lane == 0) redw[w] = lm;
    __syncthreads();
    if (t == 0) {
        float m = redw[0];
#pragma unroll
        for (int i = 1; i < 8; i++) m = fmaxf(m, redw[i]);
        s_m = m;
    }
    __syncthreads();
    const float m = s_m;
    float ls = 0.f;
    if (t < len) {
        float p = __expf(sc[t] - m);
        sc[t] = p;
        ls = p;
    }
#pragma unroll
    for (int o = 16; o; o >>= 1) ls += __shfl_xor_sync(0xffffffffu, ls, o);
    if (lane == 0) redw[w] = ls;
    __syncthreads();
    if (t == 0) {
        float l = 0.f;
#pragma unroll
        for (int i = 0; i < 8; i++) l += redw[i];
        s_l = l;
    }
    __syncthreads();

    const float* vnew = g_qkv + b * QKVN + 8192 + h * 128;
    const float* vbasep = v_cache + (size_t)b * SS * (HH * 128) + h * 128;
    const int d = t & 127;
    const int half = t >> 7;
    float acc = 0.f;
#pragma unroll 8
    for (int sl = half; sl < len; sl += 2) {
        int s = s0 + sl;
        const float* vr = (s == pos) ? vnew : (vbasep + (size_t)s * 4096);
        acc += sc[sl] * vr[d];
    }
    red[t] = acc;
    __syncthreads();
    if (t < 128) g_pacc[(size_t)pidx * 128 + t] = red[t] + red[t + 128];
    if (t == 0) {
        g_pm[pidx] = m;
        g_pl[pidx] = s_l;
    }
}

// combine the <=8 chunk partials per (b,h) -> g_attn[b][h*VD+d]
__global__ void __launch_bounds__(128) attn_combine_kernel() {
    const int bh = blockIdx.x;
    const int d = threadIdx.x;
    float M = -1e30f;
#pragma unroll
    for (int c = 0; c < NCHUNK; c++) {
        float l = g_pl[bh * NCHUNK + c];
        if (l > 0.f) M = fmaxf(M, g_pm[bh * NCHUNK + c]);
    }
    float L = 0.f, o = 0.f;
#pragma unroll
    for (int c = 0; c < NCHUNK; c++) {
        float l = g_pl[bh * NCHUNK + c];
        if (l > 0.f) {
            float wgt = __expf(g_pm[bh * NCHUNK + c] - M);
            L += l * wgt;
            o += g_pacc[(size_t)(bh * NCHUNK + c) * 128 + d] * wgt;
        }
    }
    const int b = bh >> 5, h = bh & 31;
    g_attn[b * 4096 + h * 128 + d] = o / L;
}

// sum the SPLIT2 GEMM2 split-K partials -> final output
__global__ void reduce_out_kernel(float* __restrict__ out) {
    int i = blockIdx.x * 256 + threadIdx.x;   // 131072 total
    float s = 0.f;
#pragma unroll
    for (int c = 0; c < SPLIT2; c++) s += g_p2[(size_t)c * 131072 + i];
    out[i] = s;
}

extern "C" void kernel_launch(void* const* d_in, const int* in_sizes, int n_in,
                              void* d_out, int out_size) {
    const float* hs = (const float*)d_in[0];
    const int* positions = (const int*)d_in[1];
    const float* k_cache = (const float*)d_in[2];
    const float* v_cache = (const float*)d_in[3];
    const float* Wq = (const float*)d_in[4];
    const float* Wkv = (const float*)d_in[5];
    const float* Wo = (const float*)d_in[6];
    float* out = (float*)d_out;

    float* p1;
    cudaGetSymbolAddress((void**)&p1, g_p1);
    float* p2;
    cudaGetSymbolAddress((void**)&p2, g_p2);

    const int SMEM_BYTES = (2 * 16 * WROW + 2 * 16 * 64) * 4;   // 41472
    cudaFuncSetAttribute(gemm_kernel<0>,
                         cudaFuncAttributeMaxDynamicSharedMemorySize, SMEM_BYTES);
    cudaFuncSetAttribute(gemm_kernel<1>,
                         cudaFuncAttributeMaxDynamicSharedMemorySize, SMEM_BYTES);

    // prep (slots 1-3): zero attention stats; puts gemm1 in profiled slot 4
    zero_pl_kernel<<<32, 256>>>();
    zero_pm0_kernel<<<16, 256>>>();
    zero_pm1_kernel<<<16, 256>>>();
    // 1) fused q(nope)/k/v projection: 48 N-tiles x split-K 16 (16 k-steps)
    gemm_kernel<0><<<dim3(48, SPLIT1), 256, SMEM_BYTES>>>(hs, Wq, Wkv, QKVN, 16,
                                                          p1);
    reduce_qkv_kernel<<<1536, 256>>>();
    // 2) flash-decoding attention partials
    attn_partial_kernel<<<dim3(1024, NCHUNK), 256>>>(k_cache, v_cache, positions);
    attn_combine_kernel<<<1024, 128>>>();
    // 3) output projection: 16 N-tiles x split-K 16 (16 k-steps)
    gemm_kernel<1><<<dim3(16, SPLIT2), 256, SMEM_BYTES>>>(nullptr, Wo, nullptr,
                                                          HID, 16, p2);
    reduce_out_kernel<<<512, 256>>>(out);
}

// round 12
// speedup vs baseline: 1.5461x; 1.5461x over previous
#include <cuda_runtime.h>
#include <cstdint>

// Problem constants
#define BB 32
#define SS 2048
#define HH 32
#define NOPE 128
#define VD 128
#define HID 4096
#define QKVN 12288              // 4096 q (compact nope) + 4096 k + 4096 v
#define SCALE 0.08838834764831843f   // 128^-0.5

#define NCHUNK 8
#define CHUNK 256

#define SPLIT1 32               // GEMM1 split-K
#define SPLIT2 32               // GEMM2 split-K

// ---------------- scratch (static device globals; no runtime alloc) -------------
__device__ float g_p1[(size_t)SPLIT1 * 32u * 12288u];   // GEMM1 partials (50 MB)
__device__ float g_qkv[32u * 12288u];            // fused q/k/v projections
__device__ float g_pm[1024 * NCHUNK];            // per-(b,h,chunk) running max
__device__ float g_pl[1024 * NCHUNK];            // per-(b,h,chunk) exp-sum
__device__ float g_pacc[1024 * NCHUNK * 128];    // per-chunk weighted V (4 MB)
__device__ float g_attn[32u * 4096u];            // attention output [B][H*VD]
__device__ float g_p2[(size_t)SPLIT2 * 32u * 4096u];    // GEMM2 partials (16.8 MB)

// packed f32x2 fma (Blackwell sm_100+); doubles fp32 FMA throughput
__device__ __forceinline__ unsigned long long ffma2(unsigned long long a,
                                                    unsigned long long b,
                                                    unsigned long long c) {
    unsigned long long d;
    asm("fma.rn.f32x2 %0, %1, %2, %3;" : "=l"(d) : "l"(a), "l"(b), "l"(c));
    return d;
}
// duplicate a float into both halves of a u64 (for f32x2 B-operand)
__device__ __forceinline__ unsigned long long dupf(float x) {
    unsigned u = __float_as_uint(x);
    unsigned long long r;
    asm("mov.b64 %0, {%1, %2};" : "=l"(r) : "r"(u), "r"(u));
    return r;
}
__device__ __forceinline__ void cp16(uint32_t dst, const float* src) {
    asm volatile("cp.async.cg.shared.global [%0], [%1], 16;" ::"r"(dst),
                 "l"(src)
                 : "memory");
}

// ---------------- prep kernels (also place gemm1 in ncu's profiled slot 4) ------
__global__ void zero_pl_kernel() { g_pl[blockIdx.x * 256 + threadIdx.x] = 0.f; }
__global__ void zero_pm0_kernel() { g_pm[blockIdx.x * 256 + threadIdx.x] = -1e30f; }
__global__ void zero_pm1_kernel() {
    g_pm[4096 + blockIdx.x * 256 + threadIdx.x] = -1e30f;
}

// =====================================================================
// GEMM v6: v4's PROVEN layout (cp.async W + quad-swizzle, broadcast A)
// with the per-thread tile HALVED to 16M x 2N (acc = 16 u64 = 32 regs).
// v4 was register-capped: 128 regs -> 16 warps/SM -> issue 41%. v5's
// layout change regressed (STS conflicts). v6 keeps v4's memory paths
// verbatim and buys occupancy instead: ~70 regs, __launch_bounds__(256,3)
// -> 24 warps/SM. Block tile: BN=256, BM=32 (2 m-halves), BK=16,
// double-buffered smem, cp.async W staging, register-prefetched A.
// MODE 0: W = fused Wq(nope-compact rows)+Wkv virtual rows, -> g_p1.
// MODE 1: W = Wo, A = g_attn, -> g_p2.
// Warp w: N-quadrant (w>>1)*64 (rows wl, wl+32), m-half (w&1)*16.
// =====================================================================
template <int MODE>
__global__ void __launch_bounds__(256, 3) gemm_kernel(
    const float* __restrict__ A, const float* __restrict__ W0,
    const float* __restrict__ W1, int N, int ksteps, float* __restrict__ part) {
    extern __shared__ __align__(16) float smem[];
    float(*Ws)[16] = (float(*)[16])smem;                    // [2*256][16]
    float(*As)[32] = (float(*)[32])(smem + 2 * 256 * 16);   // [2*16][32]

    const int t = threadIdx.x;
    const int w = t >> 5, l = t & 31;
    const int n0 = blockIdx.x * 256;
    const int kbase = blockIdx.y * (ksteps * 16);
    const float* Ap = (MODE == 0) ? A : g_attn;

    const int mh = (w & 1) * 16;          // m-half base (16 rows)
    const int wl = (w >> 1) * 64 + l;     // W rows wl and wl+32

    // W staging: 4 lanes per row (quad wq), rows wr = t>>2 (64/pass, 4 passes)
    const int wr = t >> 2;
    const int wq = t & 3;
    const float* wptr[4];
#pragma unroll
    for (int p = 0; p < 4; p++) {
        int n = n0 + p * 64 + wr;
        const float* row;
        if (MODE == 0)
            row = (n < 4096) ? W0 + (size_t)((n >> 7) * 192 + (n & 127)) * HID
                             : W1 + (size_t)(n - 4096) * HID;
        else
            row = W0 + (size_t)n * HID;
        wptr[p] = row + kbase + 4 * wq;
    }
    const int scol = ((wq ^ ((wr >> 1) & 3)) << 2);

    // A staging: 2 k-values per thread per step (m = t&31, k-pair = (t>>5)*2)
    const int am = t & 31;
    const int ak2 = (t >> 5) * 2;
    const float* aptr = Ap + (size_t)am * HID + kbase + ak2;

    unsigned long long accE[8], accO[8];   // m-pairs within the m-half
#pragma unroll
    for (int p = 0; p < 8; p++) {
        accE[p] = 0ull;
        accO[p] = 0ull;
    }

    // prologue: step 0 W via cp.async (group 0), A via LDG
#pragma unroll
    for (int p = 0; p < 4; p++) {
        uint32_t dst =
            (uint32_t)__cvta_generic_to_shared(&Ws[p * 64 + wr][scol]);
        cp16(dst, wptr[p]);
    }
    asm volatile("cp.async.commit_group;" ::: "memory");
    float2 aA = *(const float2*)aptr;

    for (int ks = 0; ks < ksteps; ks++) {
        const int buf = ks & 1;
        float2 aN = aA;
        if (ks + 1 < ksteps) {
            const int nb = 1 - buf;
#pragma unroll
            for (int p = 0; p < 4; p++) {
                uint32_t dst = (uint32_t)__cvta_generic_to_shared(
                    &Ws[nb * 256 + p * 64 + wr][scol]);
                cp16(dst, wptr[p] + (ks + 1) * 16);
            }
            asm volatile("cp.async.commit_group;" ::: "memory");
            aN = *(const float2*)(aptr + (ks + 1) * 16);
        }
        // stage this step's A (regs -> smem)
        As[buf * 16 + ak2][am] = aA.x;
        As[buf * 16 + ak2 + 1][am] = aA.y;
        if (ks + 1 < ksteps)
            asm volatile("cp.async.wait_group 1;" ::: "memory");
        else
            asm volatile("cp.async.wait_group 0;" ::: "memory");
        __syncthreads();
        aA = aN;

        // ---- compute 16 kk ----
        const float(*Wb)[16] = Ws + buf * 256;
        const float(*Ab)[32] = As + buf * 16;
#pragma unroll
        for (int q = 0; q < 4; q++) {
            const int c = ((q ^ ((wl >> 1) & 3)) << 2);   // same for wl+32
            float4 wEq = *(const float4*)&Wb[wl][c];
            float4 wOq = *(const float4*)&Wb[wl + 32][c];
#pragma unroll
            for (int i = 0; i < 4; i++) {
                unsigned long long w2E = dupf((&wEq.x)[i]);
                unsigned long long w2O = dupf((&wOq.x)[i]);
                const ulonglong2* ap =
                    (const ulonglong2*)&Ab[4 * q + i][mh];
#pragma unroll
                for (int j = 0; j < 4; j++) {
                    ulonglong2 v = ap[j];   // m-pairs (4j, 4j+1), (4j+2, 4j+3)
                    accE[2 * j] = ffma2(v.x, w2E, accE[2 * j]);
                    accE[2 * j + 1] = ffma2(v.y, w2E, accE[2 * j + 1]);
                    accO[2 * j] = ffma2(v.x, w2O, accO[2 * j]);
                    accO[2 * j + 1] = ffma2(v.y, w2O, accO[2 * j + 1]);
                }
            }
        }
        __syncthreads();   // compute done before next iter overwrites buf
    }

    // ---- epilogue ----
    const int nE = n0 + wl, nO = nE + 32;
    float* bE = part + (size_t)blockIdx.y * 32 * N + nE;
    float* bO = part + (size_t)blockIdx.y * 32 * N + nO;
#pragma unroll
    for (int p = 0; p < 8; p++) {
        int m0 = mh + 2 * p;
        bE[(size_t)m0 * N] = __uint_as_float((unsigned)(accE[p] & 0xffffffffull));
        bE[(size_t)(m0 + 1) * N] = __uint_as_float((unsigned)(accE[p] >> 32));
        bO[(size_t)m0 * N] = __uint_as_float((unsigned)(accO[p] & 0xffffffffull));
        bO[(size_t)(m0 + 1) * N] = __uint_as_float((unsigned)(accO[p] >> 32));
    }
}

// sum the SPLIT1 GEMM1 split-K partials -> g_qkv
__global__ void reduce_qkv_kernel() {
    int i = blockIdx.x * 256 + threadIdx.x;   // 393216 total
    float s = 0.f;
#pragma unroll
    for (int c = 0; c < SPLIT1; c++) s += g_p1[(size_t)c * 393216 + i];
    g_qkv[i] = s;
}

// =====================================================================
// Flash-decoding attention partial (AT THE MEMORY WALL: 80% DRAM, ~96%
// of the 6.35 TB/s LTS cap — unchanged). One block per (b,h,chunk).
// =====================================================================
__global__ void __launch_bounds__(256) attn_partial_kernel(
    const float* __restrict__ k_cache, const float* __restrict__ v_cache,
    const int* __restrict__ positions) {
    const int bh = blockIdx.x;
    const int c = blockIdx.y;
    const int b = bh >> 5, h = bh & 31;
    const int t = threadIdx.x, lane = t & 31, w = t >> 5;
    const int pos = positions[b];
    const int L = pos + 1;
    const int s0 = c * CHUNK;
    const int len = min(CHUNK, L - s0);
    const int pidx = bh * NCHUNK + c;
    if (len <= 0) return;   // g_pl pre-zeroed by prep kernel

    __shared__ float sc[CHUNK];
    __shared__ float red[256];
    __shared__ float redw[8];
    __shared__ float s_m, s_l;

    const float* qb = g_qkv + b * QKVN + h * 128;
    const float4 q4 = *(const float4*)(qb + lane * 4);
    const float* knew = g_qkv + b * QKVN + 4096 + h * 128;
    const float* kbasep = k_cache + (size_t)b * SS * (HH * 128) + h * 128;

    for (int sl = 4 * w; sl < len; sl += 32) {
        float4 kv[4];
        float dd[4];
#pragma unroll
        for (int i = 0; i < 4; i++) {
            int sli = sl + i;
            int s = s0 + sli;
            const float* kp = (sli < len)
                                  ? ((s == pos) ? knew
                                                : (kbasep + (size_t)s * 4096))
                                  : knew;   // safe dummy
            kv[i] = *(const float4*)(kp + lane * 4);
        }
#pragma unroll
        for (int i = 0; i < 4; i++)
            dd[i] = kv[i].x * q4.x + kv[i].y * q4.y + kv[i].z * q4.z +
                    kv[i].w * q4.w;
#pragma unroll
        for (int o = 16; o; o >>= 1) {
#pragma unroll
            for (int i = 0; i < 4; i++)
                dd[i] += __shfl_xor_sync(0xffffffffu, dd[i], o);
        }
        if (lane == 0) {
#pragma unroll
            for (int i = 0; i < 4; i++)
                if (sl + i < len) sc[sl + i] = dd[i] * SCALE;
        }
    }
    __syncthreads();

    float lm = (t < len) ? sc[t] : -1e30f;
#pragma unroll
    for (int o = 16; o; o >>= 1) lm = fmaxf(lm, __shfl_xor_sync(0xffffffffu, lm, o));
    if (lane == 0) redw[w] = lm;
    __syncthreads();
    if (t == 0) {
        float m = redw[0];
#pragma unroll
        for (int i = 1; i < 8; i++) m = fmaxf(m, redw[i]);
        s_m = m;
    }
    __syncthreads();
    const float m = s_m;
    float ls = 0.f;
    if (t < len) {
        float p = __expf(sc[t] - m);
        sc[t] = p;
        ls = p;
    }
#pragma unroll
    for (int o = 16; o; o >>= 1) ls += __shfl_xor_sync(0xffffffffu, ls, o);
    if (lane == 0) redw[w] = ls;
    __syncthreads();
    if (t == 0) {
        float l = 0.f;
#pragma unroll
        for (int i = 0; i < 8; i++) l += redw[i];
        s_l = l;
    }
    __syncthreads();

    const float* vnew = g_qkv + b * QKVN + 8192 + h * 128;
    const float* vbasep = v_cache + (size_t)b * SS * (HH * 128) + h * 128;
    const int d = t & 127;
    const int half = t >> 7;
    float acc = 0.f;
#pragma unroll 8
    for (int sl = half; sl < len; sl += 2) {
        int s = s0 + sl;
        const float* vr = (s == pos) ? vnew : (vbasep + (size_t)s * 4096);
        acc += sc[sl] * vr[d];
    }
    red[t] = acc;
    __syncthreads();
    if (t < 128) g_pacc[(size_t)pidx * 128 + t] = red[t] + red[t + 128];
    if (t == 0) {
        g_pm[pidx] = m;
        g_pl[pidx] = s_l;
    }
}

// combine the <=8 chunk partials per (b,h) -> g_attn[b][h*VD+d]
__global__ void __launch_bounds__(128) attn_combine_kernel() {
    const int bh = blockIdx.x;
    const int d = threadIdx.x;
    float M = -1e30f;
#pragma unroll
    for (int c = 0; c < NCHUNK; c++) {
        float l = g_pl[bh * NCHUNK + c];
        if (l > 0.f) M = fmaxf(M, g_pm[bh * NCHUNK + c]);
    }
    float L = 0.f, o = 0.f;
#pragma unroll
    for (int c = 0; c < NCHUNK; c++) {
        float l = g_pl[bh * NCHUNK + c];
        if (l > 0.f) {
            float wgt = __expf(g_pm[bh * NCHUNK + c] - M);
            L += l * wgt;
            o += g_pacc[(size_t)(bh * NCHUNK + c) * 128 + d] * wgt;
        }
    }
    const int b = bh >> 5, h = bh & 31;
    g_attn[b * 4096 + h * 128 + d] = o / L;
}

// sum the SPLIT2 GEMM2 split-K partials -> final output
__global__ void reduce_out_kernel(float* __restrict__ out) {
    int i = blockIdx.x * 256 + threadIdx.x;   // 131072 total
    float s = 0.f;
#pragma unroll
    for (int c = 0; c < SPLIT2; c++) s += g_p2[(size_t)c * 131072 + i];
    out[i] = s;
}

extern "C" void kernel_launch(void* const* d_in, const int* in_sizes, int n_in,
                              void* d_out, int out_size) {
    const float* hs = (const float*)d_in[0];
    const int* positions = (const int*)d_in[1];
    const float* k_cache = (const float*)d_in[2];
    const float* v_cache = (const float*)d_in[3];
    const float* Wq = (const float*)d_in[4];
    const float* Wkv = (const float*)d_in[5];
    const float* Wo = (const float*)d_in[6];
    float* out = (float*)d_out;

    float* p1;
    cudaGetSymbolAddress((void**)&p1, g_p1);
    float* p2;
    cudaGetSymbolAddress((void**)&p2, g_p2);

    const int SMEM_BYTES = (2 * 256 * 16 + 2 * 16 * 32) * 4;   // 36864
    cudaFuncSetAttribute(gemm_kernel<0>,
                         cudaFuncAttributeMaxDynamicSharedMemorySize, SMEM_BYTES);
    cudaFuncSetAttribute(gemm_kernel<1>,
                         cudaFuncAttributeMaxDynamicSharedMemorySize, SMEM_BYTES);

    // prep (slots 1-3): zero attention stats; puts gemm1 in profiled slot 4
    zero_pl_kernel<<<32, 256>>>();
    zero_pm0_kernel<<<16, 256>>>();
    zero_pm1_kernel<<<16, 256>>>();
    // 1) fused q(nope)/k/v projection: 48 N-tiles x split-K 32 (8 k-steps)
    gemm_kernel<0><<<dim3(48, SPLIT1), 256, SMEM_BYTES>>>(hs, Wq, Wkv, QKVN, 8,
                                                          p1);
    reduce_qkv_kernel<<<1536, 256>>>();
    // 2) flash-decoding attention partials
    attn_partial_kernel<<<dim3(1024, NCHUNK), 256>>>(k_cache, v_cache, positions);
    attn_combine_kernel<<<1024, 128>>>();
    // 3) output projection: 16 N-tiles x split-K 32 (8 k-steps)
    gemm_kernel<1><<<dim3(16, SPLIT2), 256, SMEM_BYTES>>>(nullptr, Wo, nullptr,
                                                          HID, 8, p2);
    reduce_out_kernel<<<512, 256>>>(out);
}